// round 1
// baseline (speedup 1.0000x reference)
#include <cuda_runtime.h>
#include <cuda_fp16.h>
#include <cstdint>

#define B_DIM 512
#define IN_F  1024
#define OUT_F 1024

// Device-global scratch (no allocation allowed in kernel_launch)
__device__ __half g_XH[B_DIM * IN_F];   // high part of quantized x (multiple of 32)
__device__ __half g_XL[B_DIM * IN_F];   // low 5 bits of quantized x
__device__ __half g_WQ[OUT_F * IN_F];   // quantized weight (fits fp16 exactly for this data)

// round-half-even then clip, matching jnp.round + jnp.clip
__device__ __forceinline__ float fixq_f(float v) {
    float q = rintf(v * 4096.0f);
    return fminf(fmaxf(q, -32768.0f), 32767.0f);
}

__global__ void quant_w_kernel(const float* __restrict__ w) {
    int i = blockIdx.x * blockDim.x + threadIdx.x;  // over float4 groups
    float4 v = reinterpret_cast<const float4*>(w)[i];
    __half2* o = reinterpret_cast<__half2*>(g_WQ);
    o[2 * i]     = __halves2half2(__float2half_rn(fixq_f(v.x)), __float2half_rn(fixq_f(v.y)));
    o[2 * i + 1] = __halves2half2(__float2half_rn(fixq_f(v.z)), __float2half_rn(fixq_f(v.w)));
}

__global__ void quant_x_kernel(const float* __restrict__ x) {
    int i = blockIdx.x * blockDim.x + threadIdx.x;  // over float4 groups
    float4 v = reinterpret_cast<const float4*>(x)[i];
    int q0 = (int)fixq_f(v.x), q1 = (int)fixq_f(v.y), q2 = (int)fixq_f(v.z), q3 = (int)fixq_f(v.w);
    int l0 = q0 & 31, l1 = q1 & 31, l2 = q2 & 31, l3 = q3 & 31;
    __half2* oh = reinterpret_cast<__half2*>(g_XH);
    __half2* ol = reinterpret_cast<__half2*>(g_XL);
    oh[2 * i]     = __halves2half2(__float2half_rn((float)(q0 - l0)), __float2half_rn((float)(q1 - l1)));
    oh[2 * i + 1] = __halves2half2(__float2half_rn((float)(q2 - l2)), __float2half_rn((float)(q3 - l3)));
    ol[2 * i]     = __halves2half2(__float2half_rn((float)l0), __float2half_rn((float)l1));
    ol[2 * i + 1] = __halves2half2(__float2half_rn((float)l2), __float2half_rn((float)l3));
}

// ---------------- GEMM: out[b,o] = quantize(sum_i (xh+xl)[b,i] * wq[o,i]) + bias[o] ---------
// CTA tile 64x64, BK=32, 4 warps (2x2), warp tile 32x32 via mma.m16n8k16.
#define BK    32
#define PITCH 40   // halves per smem row (80B: 16B-aligned, conflict-friendly)

__device__ __forceinline__ void cpa16(uint32_t s, const void* g) {
    asm volatile("cp.async.cg.shared.global [%0], [%1], 16;\n" :: "r"(s), "l"(g));
}
__device__ __forceinline__ void ldmx4(uint32_t r[4], uint32_t addr) {
    asm volatile("ldmatrix.sync.aligned.m8n8.x4.shared.b16 {%0,%1,%2,%3}, [%4];\n"
                 : "=r"(r[0]), "=r"(r[1]), "=r"(r[2]), "=r"(r[3]) : "r"(addr));
}
__device__ __forceinline__ void mma16816(float c[4], const uint32_t a[4], uint32_t b0, uint32_t b1) {
    asm volatile("mma.sync.aligned.m16n8k16.row.col.f32.f16.f16.f32 "
                 "{%0,%1,%2,%3}, {%4,%5,%6,%7}, {%8,%9}, {%0,%1,%2,%3};\n"
                 : "+f"(c[0]), "+f"(c[1]), "+f"(c[2]), "+f"(c[3])
                 : "r"(a[0]), "r"(a[1]), "r"(a[2]), "r"(a[3]), "r"(b0), "r"(b1));
}

__device__ __forceinline__ float qout(float a) {
    float r = rintf(a * 2.44140625e-4f);            // acc * 2^-12
    r = fminf(fmaxf(r, -32768.0f), 32767.0f);
    return r * 2.44140625e-4f;                      // * 2^-12
}

__global__ __launch_bounds__(128) void mvm_gemm_kernel(const float* __restrict__ bias,
                                                       float* __restrict__ out) {
    __shared__ __half smem[2][3][64 * PITCH];       // [stage][AH,AL,B][tile]

    const int tid  = threadIdx.x;
    const int lane = tid & 31;
    const int warp = tid >> 5;
    const int wm = warp >> 1, wn = warp & 1;        // 2x2 warp grid
    const int bm0 = blockIdx.y * 64;
    const int bn0 = blockIdx.x * 64;

    float acc[2][4][4];
    #pragma unroll
    for (int mi = 0; mi < 2; ++mi)
        #pragma unroll
        for (int nj = 0; nj < 4; ++nj)
            #pragma unroll
            for (int c = 0; c < 4; ++c) acc[mi][nj][c] = 0.0f;

    // cp.async mapping: 256 chunks of 16B per tile (64 rows x 4), 2 chunks/thread
    const int r0 = tid >> 2;                 // 0..31
    const int c0 = (tid & 3) * 8;            // half offset within row
    const __half* gAH = g_XH + (size_t)bm0 * IN_F;
    const __half* gAL = g_XL + (size_t)bm0 * IN_F;
    const __half* gB  = g_WQ + (size_t)bn0 * IN_F;

    auto prefetch = [&](int it) {
        int s = it & 1;
        int k0 = it * BK;
        uint32_t sAH = (uint32_t)__cvta_generic_to_shared(&smem[s][0][0]);
        uint32_t sAL = (uint32_t)__cvta_generic_to_shared(&smem[s][1][0]);
        uint32_t sB  = (uint32_t)__cvta_generic_to_shared(&smem[s][2][0]);
        cpa16(sAH + (r0 * PITCH + c0) * 2,        gAH + (size_t)r0 * IN_F + k0 + c0);
        cpa16(sAH + ((r0 + 32) * PITCH + c0) * 2, gAH + (size_t)(r0 + 32) * IN_F + k0 + c0);
        cpa16(sAL + (r0 * PITCH + c0) * 2,        gAL + (size_t)r0 * IN_F + k0 + c0);
        cpa16(sAL + ((r0 + 32) * PITCH + c0) * 2, gAL + (size_t)(r0 + 32) * IN_F + k0 + c0);
        cpa16(sB  + (r0 * PITCH + c0) * 2,        gB  + (size_t)r0 * IN_F + k0 + c0);
        cpa16(sB  + ((r0 + 32) * PITCH + c0) * 2, gB  + (size_t)(r0 + 32) * IN_F + k0 + c0);
        asm volatile("cp.async.commit_group;\n" ::: "memory");
    };

    prefetch(0);
    const int NIT = IN_F / BK;  // 32
    for (int it = 0; it < NIT; ++it) {
        asm volatile("cp.async.wait_group 0;\n" ::: "memory");
        __syncthreads();   // stage ready; also guarantees all warps done with prior compute
        if (it + 1 < NIT) prefetch(it + 1);

        int s = it & 1;
        uint32_t baseAH = (uint32_t)__cvta_generic_to_shared(&smem[s][0][0]);
        uint32_t baseAL = (uint32_t)__cvta_generic_to_shared(&smem[s][1][0]);
        uint32_t baseB  = (uint32_t)__cvta_generic_to_shared(&smem[s][2][0]);

        #pragma unroll
        for (int ks = 0; ks < 2; ++ks) {
            uint32_t aH[2][4], aL[2][4], bb[2][4];
            #pragma unroll
            for (int mi = 0; mi < 2; ++mi) {
                int roff = wm * 32 + mi * 16 + (lane & 15);
                int coff = ks * 16 + (lane >> 4) * 8;
                ldmx4(aH[mi], baseAH + (roff * PITCH + coff) * 2);
                ldmx4(aL[mi], baseAL + (roff * PITCH + coff) * 2);
            }
            #pragma unroll
            for (int j = 0; j < 2; ++j) {
                int row = wn * 32 + j * 16 + ((lane >> 4) & 1) * 8 + (lane & 7);
                int col = ks * 16 + ((lane >> 3) & 1) * 8;
                ldmx4(bb[j], baseB + (row * PITCH + col) * 2);
            }
            #pragma unroll
            for (int mi = 0; mi < 2; ++mi)
                #pragma unroll
                for (int nj = 0; nj < 4; ++nj) {
                    uint32_t blo = bb[nj >> 1][(nj & 1) * 2];
                    uint32_t bhi = bb[nj >> 1][(nj & 1) * 2 + 1];
                    mma16816(acc[mi][nj], aH[mi], blo, bhi);
                    mma16816(acc[mi][nj], aL[mi], blo, bhi);
                }
        }
    }

    // Epilogue: quantize + bias
    #pragma unroll
    for (int mi = 0; mi < 2; ++mi) {
        int gr = bm0 + wm * 32 + mi * 16 + (lane >> 2);
        #pragma unroll
        for (int nj = 0; nj < 4; ++nj) {
            int gc = bn0 + wn * 32 + nj * 8 + (lane & 3) * 2;
            float b0 = __ldg(&bias[gc]);
            float b1 = __ldg(&bias[gc + 1]);
            float2 v0, v1;
            v0.x = qout(acc[mi][nj][0]) + b0;
            v0.y = qout(acc[mi][nj][1]) + b1;
            v1.x = qout(acc[mi][nj][2]) + b0;
            v1.y = qout(acc[mi][nj][3]) + b1;
            *reinterpret_cast<float2*>(&out[(size_t)gr * OUT_F + gc]) = v0;
            *reinterpret_cast<float2*>(&out[(size_t)(gr + 8) * OUT_F + gc]) = v1;
        }
    }
}

extern "C" void kernel_launch(void* const* d_in, const int* in_sizes, int n_in,
                              void* d_out, int out_size) {
    const float* x    = (const float*)d_in[0];   // [512,1024]
    const float* w    = (const float*)d_in[1];   // [1024,1024] (out_f, in_f)
    const float* bias = (const float*)d_in[2];   // [1024]
    float* out = (float*)d_out;                  // [512,1024] float32

    quant_x_kernel<<<(B_DIM * IN_F / 4) / 256, 256>>>(x);
    quant_w_kernel<<<(OUT_F * IN_F / 4) / 256, 256>>>(w);
    dim3 grid(OUT_F / 64, B_DIM / 64);           // 16 x 8 = 128 CTAs
    mvm_gemm_kernel<<<grid, 128>>>(bias, out);
}

// round 3
// speedup vs baseline: 1.2065x; 1.2065x over previous
#include <cuda_runtime.h>
#include <cuda_fp16.h>
#include <cstdint>

#define B_DIM 512
#define IN_F  1024
#define OUT_F 1024

// Device-global scratch (no allocation allowed in kernel_launch)
__device__ __half g_XH[B_DIM * IN_F];   // high part of quantized x (multiple of 32; fp16-exact)
__device__ __half g_XL[B_DIM * IN_F];   // low 5 bits of quantized x (fp16-exact)
__device__ __half g_WQ[OUT_F * IN_F];   // quantized weight (|wq| <= ~1100, fp16-exact)

// ---------------------------------------------------------------------------
// Helpers
// ---------------------------------------------------------------------------
__device__ __forceinline__ float fixq_f(float v) {
    float q = rintf(v * 4096.0f);
    return fminf(fmaxf(q, -32768.0f), 32767.0f);
}

__device__ __forceinline__ float qout(float a) {
    float r = rintf(a * 2.44140625e-4f);            // acc * 2^-12
    r = fminf(fmaxf(r, -32768.0f), 32767.0f);
    return r * 2.44140625e-4f;                      // * 2^-12
}

__device__ __forceinline__ void cpa16(uint32_t s, const void* g) {
    asm volatile("cp.async.cg.shared.global [%0], [%1], 16;\n" :: "r"(s), "l"(g));
}
__device__ __forceinline__ void ldmx4(uint32_t r[4], uint32_t addr) {
    asm volatile("ldmatrix.sync.aligned.m8n8.x4.shared.b16 {%0,%1,%2,%3}, [%4];\n"
                 : "=r"(r[0]), "=r"(r[1]), "=r"(r[2]), "=r"(r[3]) : "r"(addr));
}
__device__ __forceinline__ void mma16816(float c[4], const uint32_t a[4], uint32_t b0, uint32_t b1) {
    asm volatile("mma.sync.aligned.m16n8k16.row.col.f32.f16.f16.f32 "
                 "{%0,%1,%2,%3}, {%4,%5,%6,%7}, {%8,%9}, {%0,%1,%2,%3};\n"
                 : "+f"(c[0]), "+f"(c[1]), "+f"(c[2]), "+f"(c[3])
                 : "r"(a[0]), "r"(a[1]), "r"(a[2]), "r"(a[3]), "r"(b0), "r"(b1));
}

// ---------------------------------------------------------------------------
// Fused quantization: blocks [0,256) handle x (split into XH/XL), [256,768) handle w.
// 8 floats per thread, fully 16B-vectorized loads and stores.
// ---------------------------------------------------------------------------
__global__ __launch_bounds__(256) void quant_kernel(const float* __restrict__ x,
                                                    const float* __restrict__ w) {
    int b = blockIdx.x, t = threadIdx.x;
    if (b < 256) {
        int base = (b * 256 + t) * 8;
        float4 v0 = *reinterpret_cast<const float4*>(x + base);
        float4 v1 = *reinterpret_cast<const float4*>(x + base + 4);
        float f[8] = {v0.x, v0.y, v0.z, v0.w, v1.x, v1.y, v1.z, v1.w};
        __half h[8], l[8];
        #pragma unroll
        for (int i = 0; i < 8; i++) {
            int q = (int)fixq_f(f[i]);
            int lo = q & 31;
            h[i] = __float2half_rn((float)(q - lo));
            l[i] = __float2half_rn((float)lo);
        }
        *reinterpret_cast<uint4*>(g_XH + base) = *reinterpret_cast<uint4*>(h);
        *reinterpret_cast<uint4*>(g_XL + base) = *reinterpret_cast<uint4*>(l);
    } else {
        int base = ((b - 256) * 256 + t) * 8;
        float4 v0 = *reinterpret_cast<const float4*>(w + base);
        float4 v1 = *reinterpret_cast<const float4*>(w + base + 4);
        float f[8] = {v0.x, v0.y, v0.z, v0.w, v1.x, v1.y, v1.z, v1.w};
        __half h[8];
        #pragma unroll
        for (int i = 0; i < 8; i++) h[i] = __float2half_rn(fixq_f(f[i]));
        *reinterpret_cast<uint4*>(g_WQ + base) = *reinterpret_cast<uint4*>(h);
    }
}

// ---------------------------------------------------------------------------
// GEMM: out[b,o] = qout(sum_k (XH+XL)[b,k] * WQ[o,k]) + bias[o]
// CTA tile 64x64, 256 threads (8 warps, 2x4 warp grid, warp tile 32x16),
// BK=64, 4-stage cp.async pipeline, one __syncthreads per K-iteration.
// Grid: (16, 8) = 128 CTAs.
// ---------------------------------------------------------------------------
#define BK      64
#define NIT     (IN_F / BK)     // 16
#define PITCH   72              // halves per smem row (144B; conflict-free for ldmatrix)
#define MAT_H   (64 * PITCH)    // halves per matrix tile
#define STAGE_H (3 * MAT_H)     // AH, AL, B
#define NSTAGES 4
#define SMEM_BYTES (NSTAGES * STAGE_H * 2)   // 110592

__global__ __launch_bounds__(256) void mvm_gemm_kernel(const float* __restrict__ bias,
                                                       float* __restrict__ out) {
    extern __shared__ __align__(128) __half smem[];

    const int tid  = threadIdx.x;
    const int lane = tid & 31;
    const int warp = tid >> 5;
    const int wm = warp >> 2, wn = warp & 3;        // 2x4 warp grid
    const int bm0 = blockIdx.y * 64;
    const int bn0 = blockIdx.x * 64;

    float acc[2][2][4];
    #pragma unroll
    for (int mi = 0; mi < 2; ++mi)
        #pragma unroll
        for (int nj = 0; nj < 2; ++nj)
            #pragma unroll
            for (int c = 0; c < 4; ++c) acc[mi][nj][c] = 0.0f;

    const __half* gAH = g_XH + (size_t)bm0 * IN_F;
    const __half* gAL = g_XL + (size_t)bm0 * IN_F;
    const __half* gB  = g_WQ + (size_t)bn0 * IN_F;

    // cp.async mapping: 64 rows x 8 chunks(16B) per matrix = 512 chunks;
    // 256 threads -> 2 chunks/thread/matrix. 4 threads per row, 2 consecutive chunks each.
    const int r0 = tid >> 2;                 // 0..63
    const int ch0 = (tid & 3) * 2;           // chunk {0,2,4,6}
    const uint32_t smem_base = (uint32_t)__cvta_generic_to_shared(smem);

    auto prefetch = [&](int p) {
        const int s = p & (NSTAGES - 1);
        const uint32_t so = smem_base + s * (STAGE_H * 2);
        const int k0 = p * BK;
        const __half* aH = gAH + (size_t)r0 * IN_F + k0;
        const __half* aL = gAL + (size_t)r0 * IN_F + k0;
        const __half* bw = gB  + (size_t)r0 * IN_F + k0;
        #pragma unroll
        for (int j = 0; j < 2; ++j) {
            const int col = (ch0 + j) * 8;
            const uint32_t d = so + (r0 * PITCH + col) * 2;
            cpa16(d,               aH + col);
            cpa16(d + MAT_H * 2,   aL + col);
            cpa16(d + MAT_H * 4,   bw + col);
        }
        asm volatile("cp.async.commit_group;\n" ::: "memory");
    };

    prefetch(0); prefetch(1); prefetch(2);

    for (int it = 0; it < NIT; ++it) {
        // Wait for stage `it` (own groups), then barrier so all threads' data is visible
        if      (it < NIT - 2) asm volatile("cp.async.wait_group 2;\n" ::: "memory");
        else if (it == NIT - 2) asm volatile("cp.async.wait_group 1;\n" ::: "memory");
        else                    asm volatile("cp.async.wait_group 0;\n" ::: "memory");
        __syncthreads();
        // Now safe to overwrite stage (it+3)%4 == (it-1)%4: all warps are past iter it-1
        if (it + 3 < NIT) prefetch(it + 3);

        const int s = it & (NSTAGES - 1);
        const uint32_t so = smem_base + s * (STAGE_H * 2);
        const uint32_t baseAH = so;
        const uint32_t baseAL = so + MAT_H * 2;
        const uint32_t baseB  = so + MAT_H * 4;

        #pragma unroll
        for (int ks = 0; ks < 4; ++ks) {
            uint32_t aH[2][4], aL[2][4], bb[4];
            #pragma unroll
            for (int mi = 0; mi < 2; ++mi) {
                const int roff = wm * 32 + mi * 16 + (lane & 15);
                const int coff = ks * 16 + (lane >> 4) * 8;
                ldmx4(aH[mi], baseAH + (roff * PITCH + coff) * 2);
                ldmx4(aL[mi], baseAL + (roff * PITCH + coff) * 2);
            }
            {
                const int row = wn * 16 + ((lane >> 4) & 1) * 8 + (lane & 7);
                const int col = ks * 16 + ((lane >> 3) & 1) * 8;
                ldmx4(bb, baseB + (row * PITCH + col) * 2);
            }
            #pragma unroll
            for (int mi = 0; mi < 2; ++mi)
                #pragma unroll
                for (int nj = 0; nj < 2; ++nj) {
                    mma16816(acc[mi][nj], aH[mi], bb[nj * 2], bb[nj * 2 + 1]);
                    mma16816(acc[mi][nj], aL[mi], bb[nj * 2], bb[nj * 2 + 1]);
                }
        }
    }

    // Epilogue: quantize + bias
    #pragma unroll
    for (int mi = 0; mi < 2; ++mi) {
        const int gr = bm0 + wm * 32 + mi * 16 + (lane >> 2);
        #pragma unroll
        for (int nj = 0; nj < 2; ++nj) {
            const int gc = bn0 + wn * 16 + nj * 8 + (lane & 3) * 2;
            const float b0 = __ldg(&bias[gc]);
            const float b1 = __ldg(&bias[gc + 1]);
            float2 v0, v1;
            v0.x = qout(acc[mi][nj][0]) + b0;
            v0.y = qout(acc[mi][nj][1]) + b1;
            v1.x = qout(acc[mi][nj][2]) + b0;
            v1.y = qout(acc[mi][nj][3]) + b1;
            *reinterpret_cast<float2*>(&out[(size_t)gr * OUT_F + gc]) = v0;
            *reinterpret_cast<float2*>(&out[(size_t)(gr + 8) * OUT_F + gc]) = v1;
        }
    }
}

extern "C" void kernel_launch(void* const* d_in, const int* in_sizes, int n_in,
                              void* d_out, int out_size) {
    const float* x    = (const float*)d_in[0];   // [512,1024]
    const float* w    = (const float*)d_in[1];   // [1024,1024] (out_f, in_f)
    const float* bias = (const float*)d_in[2];   // [1024]
    float* out = (float*)d_out;                  // [512,1024] float32

    cudaFuncSetAttribute(mvm_gemm_kernel,
                         cudaFuncAttributeMaxDynamicSharedMemorySize, SMEM_BYTES);

    quant_kernel<<<768, 256>>>(x, w);
    dim3 grid(OUT_F / 64, B_DIM / 64);           // 16 x 8 = 128 CTAs
    mvm_gemm_kernel<<<grid, 256, SMEM_BYTES>>>(bias, out);
}

// round 4
// speedup vs baseline: 1.2179x; 1.0094x over previous
#include <cuda_runtime.h>
#include <cuda_fp16.h>
#include <cstdint>

#define B_DIM 512
#define IN_F  1024
#define OUT_F 1024

// Device-global scratch (no allocation allowed in kernel_launch)
__device__ __half g_XH[B_DIM * IN_F];   // high part of quantized x (multiple of 32; fp16-exact)
__device__ __half g_XL[B_DIM * IN_F];   // low 5 bits of quantized x (fp16-exact)
__device__ __half g_WQ[OUT_F * IN_F];   // quantized weight (fp16-exact for this data)

// ---------------------------------------------------------------------------
// Helpers
// ---------------------------------------------------------------------------
__device__ __forceinline__ float fixq_f(float v) {
    float q = rintf(v * 4096.0f);
    return fminf(fmaxf(q, -32768.0f), 32767.0f);
}

__device__ __forceinline__ float qout(float a) {
    float r = rintf(a * 2.44140625e-4f);            // acc * 2^-12
    r = fminf(fmaxf(r, -32768.0f), 32767.0f);
    return r * 2.44140625e-4f;                      // * 2^-12
}

__device__ __forceinline__ void cpa16(uint32_t s, const void* g) {
    asm volatile("cp.async.cg.shared.global [%0], [%1], 16;\n" :: "r"(s), "l"(g));
}
__device__ __forceinline__ void ldmx4(uint32_t r[4], uint32_t addr) {
    asm volatile("ldmatrix.sync.aligned.m8n8.x4.shared.b16 {%0,%1,%2,%3}, [%4];\n"
                 : "=r"(r[0]), "=r"(r[1]), "=r"(r[2]), "=r"(r[3]) : "r"(addr));
}
__device__ __forceinline__ void mma16816(float c[4], const uint32_t a[4], uint32_t b0, uint32_t b1) {
    asm volatile("mma.sync.aligned.m16n8k16.row.col.f32.f16.f16.f32 "
                 "{%0,%1,%2,%3}, {%4,%5,%6,%7}, {%8,%9}, {%0,%1,%2,%3};\n"
                 : "+f"(c[0]), "+f"(c[1]), "+f"(c[2]), "+f"(c[3])
                 : "r"(a[0]), "r"(a[1]), "r"(a[2]), "r"(a[3]), "r"(b0), "r"(b1));
}

// ---------------------------------------------------------------------------
// Fused quantization: blocks [0,256) handle x (split into XH/XL), [256,768) handle w.
// ---------------------------------------------------------------------------
__global__ __launch_bounds__(256) void quant_kernel(const float* __restrict__ x,
                                                    const float* __restrict__ w) {
    int b = blockIdx.x, t = threadIdx.x;
    if (b < 256) {
        int base = (b * 256 + t) * 8;
        float4 v0 = *reinterpret_cast<const float4*>(x + base);
        float4 v1 = *reinterpret_cast<const float4*>(x + base + 4);
        float f[8] = {v0.x, v0.y, v0.z, v0.w, v1.x, v1.y, v1.z, v1.w};
        __half h[8], l[8];
        #pragma unroll
        for (int i = 0; i < 8; i++) {
            int q = (int)fixq_f(f[i]);
            int lo = q & 31;
            h[i] = __float2half_rn((float)(q - lo));
            l[i] = __float2half_rn((float)lo);
        }
        *reinterpret_cast<uint4*>(g_XH + base) = *reinterpret_cast<uint4*>(h);
        *reinterpret_cast<uint4*>(g_XL + base) = *reinterpret_cast<uint4*>(l);
    } else {
        int base = ((b - 256) * 256 + t) * 8;
        float4 v0 = *reinterpret_cast<const float4*>(w + base);
        float4 v1 = *reinterpret_cast<const float4*>(w + base + 4);
        float f[8] = {v0.x, v0.y, v0.z, v0.w, v1.x, v1.y, v1.z, v1.w};
        __half h[8];
        #pragma unroll
        for (int i = 0; i < 8; i++) h[i] = __float2half_rn(fixq_f(f[i]));
        *reinterpret_cast<uint4*>(g_WQ + base) = *reinterpret_cast<uint4*>(h);
    }
}

// ---------------------------------------------------------------------------
// GEMM: out[b,o] = qout(sum_k (XH+XL)[b,k] * WQ[o,k]) + bias[o]
// CTA tile 64x64, 256 threads (8 warps, 4x2 warp grid, warp tile 16x32),
// BK=64, 4-stage cp.async pipeline, fragment double-buffering across ks.
// Grid: (16, 8) = 128 CTAs.
// ---------------------------------------------------------------------------
#define BK        64
#define NIT       (IN_F / BK)     // 16
#define PITCH     72              // halves per smem row (144B; conflict-free)
#define MAT_B     (64 * PITCH * 2)  // bytes per matrix tile (9216)
#define STAGE_B   (3 * MAT_B)       // AH, AL, B (27648)
#define NSTAGES   4
#define SMEM_BYTES (NSTAGES * STAGE_B)   // 110592

__global__ __launch_bounds__(256) void mvm_gemm_kernel(const float* __restrict__ bias,
                                                       float* __restrict__ out) {
    extern __shared__ __align__(128) __half smem[];

    const int tid  = threadIdx.x;
    const int lane = tid & 31;
    const int warp = tid >> 5;
    const int wm = warp >> 1, wn = warp & 1;        // 4x2 warp grid, warp tile 16x32
    const int bm0 = blockIdx.y * 64;
    const int bn0 = blockIdx.x * 64;

    float acc[4][4];
    #pragma unroll
    for (int nj = 0; nj < 4; ++nj)
        #pragma unroll
        for (int c = 0; c < 4; ++c) acc[nj][c] = 0.0f;

    const __half* gAH = g_XH + (size_t)bm0 * IN_F;
    const __half* gAL = g_XL + (size_t)bm0 * IN_F;
    const __half* gB  = g_WQ + (size_t)bn0 * IN_F;

    // cp.async mapping: 64 rows x 8 chunks(16B) per matrix = 512 chunks;
    // 256 threads -> 2 chunks/thread/matrix (4 threads per row).
    const int r0 = tid >> 2;
    const int ch0 = (tid & 3) * 2;
    const uint32_t smem_base = (uint32_t)__cvta_generic_to_shared(smem);

    auto prefetch = [&](int p) {
        const int s = p & (NSTAGES - 1);
        const uint32_t so = smem_base + s * STAGE_B;
        const int k0 = p * BK;
        const __half* aH = gAH + (size_t)r0 * IN_F + k0;
        const __half* aL = gAL + (size_t)r0 * IN_F + k0;
        const __half* bw = gB  + (size_t)r0 * IN_F + k0;
        #pragma unroll
        for (int j = 0; j < 2; ++j) {
            const int col = (ch0 + j) * 8;
            const uint32_t d = so + (r0 * PITCH + col) * 2;
            cpa16(d,             aH + col);
            cpa16(d + MAT_B,     aL + col);
            cpa16(d + MAT_B * 2, bw + col);
        }
        asm volatile("cp.async.commit_group;\n" ::: "memory");
    };

    prefetch(0); prefetch(1); prefetch(2);

    // Per-lane fragment byte offsets (within a stage)
    const uint32_t laneA  = ((wm * 16 + (lane & 15)) * PITCH + (lane >> 4) * 8) * 2;
    const uint32_t laneB0 = ((wn * 32 + ((lane >> 4) & 1) * 8 + (lane & 7)) * PITCH
                             + ((lane >> 3) & 1) * 8) * 2;
    const uint32_t laneB1 = laneB0 + 16 * PITCH * 2;

    for (int it = 0; it < NIT; ++it) {
        if      (it < NIT - 2)  asm volatile("cp.async.wait_group 2;\n" ::: "memory");
        else if (it == NIT - 2) asm volatile("cp.async.wait_group 1;\n" ::: "memory");
        else                    asm volatile("cp.async.wait_group 0;\n" ::: "memory");
        __syncthreads();
        if (it + 3 < NIT) prefetch(it + 3);

        const int s = it & (NSTAGES - 1);
        const uint32_t so   = smem_base + s * STAGE_B;
        const uint32_t aHad = so + laneA;
        const uint32_t aLad = so + MAT_B + laneA;
        const uint32_t bad0 = so + MAT_B * 2 + laneB0;
        const uint32_t bad1 = so + MAT_B * 2 + laneB1;

        // Fragment double-buffering: load ks+1 while computing ks
        uint32_t aH[2][4], aL[2][4], bb[2][2][4];
        ldmx4(aH[0], aHad);
        ldmx4(aL[0], aLad);
        ldmx4(bb[0][0], bad0);
        ldmx4(bb[0][1], bad1);

        #pragma unroll
        for (int ks = 0; ks < 4; ++ks) {
            const int cur = ks & 1, nxt = cur ^ 1;
            if (ks < 3) {
                const uint32_t ko = (ks + 1) * 32;    // 16 halves = 32 bytes per ks
                ldmx4(aH[nxt], aHad + ko);
                ldmx4(aL[nxt], aLad + ko);
                ldmx4(bb[nxt][0], bad0 + ko);
                ldmx4(bb[nxt][1], bad1 + ko);
            }
            #pragma unroll
            for (int nj = 0; nj < 4; ++nj) {
                const uint32_t blo = bb[cur][nj >> 1][(nj & 1) * 2];
                const uint32_t bhi = bb[cur][nj >> 1][(nj & 1) * 2 + 1];
                mma16816(acc[nj], aH[cur], blo, bhi);
                mma16816(acc[nj], aL[cur], blo, bhi);
            }
        }
    }

    // Epilogue: quantize + bias
    const int gr = bm0 + wm * 16 + (lane >> 2);
    #pragma unroll
    for (int nj = 0; nj < 4; ++nj) {
        const int gc = bn0 + wn * 32 + nj * 8 + (lane & 3) * 2;
        const float b0 = __ldg(&bias[gc]);
        const float b1 = __ldg(&bias[gc + 1]);
        float2 v0, v1;
        v0.x = qout(acc[nj][0]) + b0;
        v0.y = qout(acc[nj][1]) + b1;
        v1.x = qout(acc[nj][2]) + b0;
        v1.y = qout(acc[nj][3]) + b1;
        *reinterpret_cast<float2*>(&out[(size_t)gr * OUT_F + gc]) = v0;
        *reinterpret_cast<float2*>(&out[(size_t)(gr + 8) * OUT_F + gc]) = v1;
    }
}

extern "C" void kernel_launch(void* const* d_in, const int* in_sizes, int n_in,
                              void* d_out, int out_size) {
    const float* x    = (const float*)d_in[0];   // [512,1024]
    const float* w    = (const float*)d_in[1];   // [1024,1024] (out_f, in_f)
    const float* bias = (const float*)d_in[2];   // [1024]
    float* out = (float*)d_out;                  // [512,1024] float32

    cudaFuncSetAttribute(mvm_gemm_kernel,
                         cudaFuncAttributeMaxDynamicSharedMemorySize, SMEM_BYTES);

    quant_kernel<<<768, 256>>>(x, w);
    dim3 grid(OUT_F / 64, B_DIM / 64);           // 16 x 8 = 128 CTAs
    mvm_gemm_kernel<<<grid, 256, SMEM_BYTES>>>(bias, out);
}

// round 5
// speedup vs baseline: 1.3373x; 1.0981x over previous
#include <cuda_runtime.h>
#include <cuda_fp16.h>
#include <cstdint>

#define B_DIM 512
#define IN_F  1024
#define OUT_F 1024

// Device-global scratch (no allocation allowed in kernel_launch)
__device__ __half g_XH[B_DIM * IN_F];   // high part of quantized x (multiple of 32; fp16-exact)
__device__ __half g_XL[B_DIM * IN_F];   // low 5 bits of quantized x (fp16-exact)
__device__ __half g_WQ[OUT_F * IN_F];   // quantized weight (fp16-exact for this data)

// ---------------------------------------------------------------------------
// Helpers
// ---------------------------------------------------------------------------
__device__ __forceinline__ float fixq_f(float v) {
    float q = rintf(v * 4096.0f);
    return fminf(fmaxf(q, -32768.0f), 32767.0f);
}

__device__ __forceinline__ float qout(float a) {
    float r = rintf(a * 2.44140625e-4f);            // acc * 2^-12
    r = fminf(fmaxf(r, -32768.0f), 32767.0f);
    return r * 2.44140625e-4f;                      // * 2^-12
}

__device__ __forceinline__ void cpa16(uint32_t s, const void* g) {
    asm volatile("cp.async.cg.shared.global [%0], [%1], 16;\n" :: "r"(s), "l"(g));
}
__device__ __forceinline__ void ldmx4(uint32_t r[4], uint32_t addr) {
    asm volatile("ldmatrix.sync.aligned.m8n8.x4.shared.b16 {%0,%1,%2,%3}, [%4];\n"
                 : "=r"(r[0]), "=r"(r[1]), "=r"(r[2]), "=r"(r[3]) : "r"(addr));
}
__device__ __forceinline__ void mma16816(float c[4], const uint32_t a[4], uint32_t b0, uint32_t b1) {
    asm volatile("mma.sync.aligned.m16n8k16.row.col.f32.f16.f16.f32 "
                 "{%0,%1,%2,%3}, {%4,%5,%6,%7}, {%8,%9}, {%0,%1,%2,%3};\n"
                 : "+f"(c[0]), "+f"(c[1]), "+f"(c[2]), "+f"(c[3])
                 : "r"(a[0]), "r"(a[1]), "r"(a[2]), "r"(a[3]), "r"(b0), "r"(b1));
}

// ---------------------------------------------------------------------------
// Fused quantization: blocks [0,256) handle x (split into XH/XL), [256,768) handle w.
// ---------------------------------------------------------------------------
__global__ __launch_bounds__(256) void quant_kernel(const float* __restrict__ x,
                                                    const float* __restrict__ w) {
    int b = blockIdx.x, t = threadIdx.x;
    if (b < 256) {
        int base = (b * 256 + t) * 8;
        float4 v0 = *reinterpret_cast<const float4*>(x + base);
        float4 v1 = *reinterpret_cast<const float4*>(x + base + 4);
        float f[8] = {v0.x, v0.y, v0.z, v0.w, v1.x, v1.y, v1.z, v1.w};
        __half h[8], l[8];
        #pragma unroll
        for (int i = 0; i < 8; i++) {
            int q = (int)fixq_f(f[i]);
            int lo = q & 31;
            h[i] = __float2half_rn((float)(q - lo));
            l[i] = __float2half_rn((float)lo);
        }
        *reinterpret_cast<uint4*>(g_XH + base) = *reinterpret_cast<uint4*>(h);
        *reinterpret_cast<uint4*>(g_XL + base) = *reinterpret_cast<uint4*>(l);
    } else {
        int base = ((b - 256) * 256 + t) * 8;
        float4 v0 = *reinterpret_cast<const float4*>(w + base);
        float4 v1 = *reinterpret_cast<const float4*>(w + base + 4);
        float f[8] = {v0.x, v0.y, v0.z, v0.w, v1.x, v1.y, v1.z, v1.w};
        __half h[8];
        #pragma unroll
        for (int i = 0; i < 8; i++) h[i] = __float2half_rn(fixq_f(f[i]));
        *reinterpret_cast<uint4*>(g_WQ + base) = *reinterpret_cast<uint4*>(h);
    }
}

// ---------------------------------------------------------------------------
// GEMM: out[b,o] = qout(sum_k (XH+XL)[b,k] * WQ[o,k]) + bias[o]
// CTA tile 64x64, 512 threads / 16 warps.
// Warp-level split-K: k-group 0 (warps 0-7) does ks 0-1 of each BK=64 stage,
// k-group 1 (warps 8-15) does ks 2-3. Warp tile 16x32, warp grid 4x2 per group.
// Final smem reduction adds the two accumulator halves.
// Grid: (16, 8) = 128 CTAs.
// ---------------------------------------------------------------------------
#define BK        64
#define NIT       (IN_F / BK)       // 16
#define PITCH     72                // halves per smem row (144B; conflict-free)
#define MAT_B     (64 * PITCH * 2)  // bytes per matrix tile (9216)
#define STAGE_B   (3 * MAT_B)       // AH, AL, B (27648)
#define NSTAGES   4
#define SMEM_BYTES (NSTAGES * STAGE_B)   // 110592

__global__ __launch_bounds__(512) void mvm_gemm_kernel(const float* __restrict__ bias,
                                                       float* __restrict__ out) {
    extern __shared__ __align__(128) __half smem[];

    const int tid  = threadIdx.x;
    const int lane = tid & 31;
    const int warp = tid >> 5;        // 0..15
    const int kg   = warp >> 3;       // k-group: 0 or 1
    const int wsub = warp & 7;        // warp id within group
    const int wm = wsub >> 1, wn = wsub & 1;   // 4x2 warp grid, warp tile 16x32
    const int bm0 = blockIdx.y * 64;
    const int bn0 = blockIdx.x * 64;

    float acc[4][4];
    #pragma unroll
    for (int nj = 0; nj < 4; ++nj)
        #pragma unroll
        for (int c = 0; c < 4; ++c) acc[nj][c] = 0.0f;

    const __half* gAH = g_XH + (size_t)bm0 * IN_F;
    const __half* gAL = g_XL + (size_t)bm0 * IN_F;
    const __half* gB  = g_WQ + (size_t)bn0 * IN_F;

    // cp.async: 64 rows x 8 chunks(16B) per matrix = 512 chunks; 512 threads -> 1/matrix
    const int r0 = tid >> 3;          // 0..63
    const int ch = tid & 7;           // chunk 0..7
    const uint32_t smem_base = (uint32_t)__cvta_generic_to_shared(smem);

    auto prefetch = [&](int p) {
        const int s = p & (NSTAGES - 1);
        const uint32_t so = smem_base + s * STAGE_B;
        const int k0 = p * BK + ch * 8;
        const uint32_t d = so + (r0 * PITCH + ch * 8) * 2;
        cpa16(d,             gAH + (size_t)r0 * IN_F + k0);
        cpa16(d + MAT_B,     gAL + (size_t)r0 * IN_F + k0);
        cpa16(d + MAT_B * 2, gB  + (size_t)r0 * IN_F + k0);
        asm volatile("cp.async.commit_group;\n" ::: "memory");
    };

    prefetch(0); prefetch(1); prefetch(2);

    // Per-lane fragment byte offsets (within a stage); k-group offset = kg*2 ks = kg*64B
    const uint32_t kgo   = kg * 64;
    const uint32_t laneA  = ((wm * 16 + (lane & 15)) * PITCH + (lane >> 4) * 8) * 2 + kgo;
    const uint32_t laneB0 = ((wn * 32 + ((lane >> 4) & 1) * 8 + (lane & 7)) * PITCH
                             + ((lane >> 3) & 1) * 8) * 2 + kgo;
    const uint32_t laneB1 = laneB0 + 16 * PITCH * 2;

    for (int it = 0; it < NIT; ++it) {
        if      (it < NIT - 2)  asm volatile("cp.async.wait_group 2;\n" ::: "memory");
        else if (it == NIT - 2) asm volatile("cp.async.wait_group 1;\n" ::: "memory");
        else                    asm volatile("cp.async.wait_group 0;\n" ::: "memory");
        __syncthreads();
        if (it + 3 < NIT) prefetch(it + 3);

        const int s = it & (NSTAGES - 1);
        const uint32_t so   = smem_base + s * STAGE_B;
        const uint32_t aHad = so + laneA;
        const uint32_t aLad = so + MAT_B + laneA;
        const uint32_t bad0 = so + MAT_B * 2 + laneB0;
        const uint32_t bad1 = so + MAT_B * 2 + laneB1;

        // This k-group handles ks = kg*2 + {0,1}; fragment double-buffer across the 2
        uint32_t aH[2][4], aL[2][4], bb[2][2][4];
        ldmx4(aH[0], aHad);
        ldmx4(aL[0], aLad);
        ldmx4(bb[0][0], bad0);
        ldmx4(bb[0][1], bad1);
        ldmx4(aH[1], aHad + 32);
        ldmx4(aL[1], aLad + 32);
        ldmx4(bb[1][0], bad0 + 32);
        ldmx4(bb[1][1], bad1 + 32);

        #pragma unroll
        for (int j = 0; j < 2; ++j)
            #pragma unroll
            for (int nj = 0; nj < 4; ++nj) {
                const uint32_t blo = bb[j][nj >> 1][(nj & 1) * 2];
                const uint32_t bhi = bb[j][nj >> 1][(nj & 1) * 2 + 1];
                mma16816(acc[nj], aH[j], blo, bhi);
                mma16816(acc[nj], aL[j], blo, bhi);
            }
    }

    // ---- Cross-k-group reduction through smem ----
    // Layout: [wsub][q][lane] float4  -> conflict-friendly (16B stride across lanes)
    float4* red = reinterpret_cast<float4*>(smem);
    __syncthreads();                  // all stages consumed; smem reusable
    if (kg == 1) {
        #pragma unroll
        for (int q = 0; q < 4; ++q) {
            float4 v;
            v.x = acc[q][0]; v.y = acc[q][1]; v.z = acc[q][2]; v.w = acc[q][3];
            red[(wsub * 4 + q) * 32 + lane] = v;
        }
    }
    __syncthreads();
    if (kg == 0) {
        const int gr = bm0 + wm * 16 + (lane >> 2);
        #pragma unroll
        for (int nj = 0; nj < 4; ++nj) {
            float4 o = red[(wsub * 4 + nj) * 32 + lane];
            const int gc = bn0 + wn * 32 + nj * 8 + (lane & 3) * 2;
            const float b0 = __ldg(&bias[gc]);
            const float b1 = __ldg(&bias[gc + 1]);
            float2 v0, v1;
            v0.x = qout(acc[nj][0] + o.x) + b0;
            v0.y = qout(acc[nj][1] + o.y) + b1;
            v1.x = qout(acc[nj][2] + o.z) + b0;
            v1.y = qout(acc[nj][3] + o.w) + b1;
            *reinterpret_cast<float2*>(&out[(size_t)gr * OUT_F + gc]) = v0;
            *reinterpret_cast<float2*>(&out[(size_t)(gr + 8) * OUT_F + gc]) = v1;
        }
    }
}

extern "C" void kernel_launch(void* const* d_in, const int* in_sizes, int n_in,
                              void* d_out, int out_size) {
    const float* x    = (const float*)d_in[0];   // [512,1024]
    const float* w    = (const float*)d_in[1];   // [1024,1024] (out_f, in_f)
    const float* bias = (const float*)d_in[2];   // [1024]
    float* out = (float*)d_out;                  // [512,1024] float32

    cudaFuncSetAttribute(mvm_gemm_kernel,
                         cudaFuncAttributeMaxDynamicSharedMemorySize, SMEM_BYTES);

    quant_kernel<<<768, 256>>>(x, w);
    dim3 grid(OUT_F / 64, B_DIM / 64);           // 16 x 8 = 128 CTAs
    mvm_gemm_kernel<<<grid, 512, SMEM_BYTES>>>(bias, out);
}

// round 7
// speedup vs baseline: 1.7305x; 1.2940x over previous
#include <cuda_runtime.h>
#include <cuda_fp16.h>
#include <cstdint>

#define B_DIM 512
#define IN_F  1024
#define OUT_F 1024

// Device-global scratch (no allocation allowed in kernel_launch)
__device__ __half g_XQ[B_DIM * IN_F];   // fp16(round-nearest) of quantized x
__device__ __half g_WQ[OUT_F * IN_F];   // quantized weight (fp16-exact for this data)

// ---------------------------------------------------------------------------
// Helpers
// ---------------------------------------------------------------------------
__device__ __forceinline__ float fixq_f(float v) {
    float q = rintf(v * 4096.0f);
    return fminf(fmaxf(q, -32768.0f), 32767.0f);
}

__device__ __forceinline__ float qout(float a) {
    float r = rintf(a * 2.44140625e-4f);            // acc * 2^-12
    r = fminf(fmaxf(r, -32768.0f), 32767.0f);
    return r * 2.44140625e-4f;                      // * 2^-12
}

__device__ __forceinline__ void cpa16(uint32_t s, const void* g) {
    asm volatile("cp.async.cg.shared.global [%0], [%1], 16;\n" :: "r"(s), "l"(g));
}
__device__ __forceinline__ void ldmx4(uint32_t r[4], uint32_t addr) {
    asm volatile("ldmatrix.sync.aligned.m8n8.x4.shared.b16 {%0,%1,%2,%3}, [%4];\n"
                 : "=r"(r[0]), "=r"(r[1]), "=r"(r[2]), "=r"(r[3]) : "r"(addr));
}
__device__ __forceinline__ void mma16816(float c[4], const uint32_t a[4], uint32_t b0, uint32_t b1) {
    asm volatile("mma.sync.aligned.m16n8k16.row.col.f32.f16.f16.f32 "
                 "{%0,%1,%2,%3}, {%4,%5,%6,%7}, {%8,%9}, {%0,%1,%2,%3};\n"
                 : "+f"(c[0]), "+f"(c[1]), "+f"(c[2]), "+f"(c[3])
                 : "r"(a[0]), "r"(a[1]), "r"(a[2]), "r"(a[3]), "r"(b0), "r"(b1));
}

// ---------------------------------------------------------------------------
// Fused quantization: blocks [0,256) handle x, [256,768) handle w.
// 8 floats per thread, fully 16B-vectorized loads and stores.
// ---------------------------------------------------------------------------
__global__ __launch_bounds__(256) void quant_kernel(const float* __restrict__ x,
                                                    const float* __restrict__ w) {
    int b = blockIdx.x, t = threadIdx.x;
    if (b < 256) {
        int base = (b * 256 + t) * 8;
        float4 v0 = *reinterpret_cast<const float4*>(x + base);
        float4 v1 = *reinterpret_cast<const float4*>(x + base + 4);
        float f[8] = {v0.x, v0.y, v0.z, v0.w, v1.x, v1.y, v1.z, v1.w};
        __half h[8];
        #pragma unroll
        for (int i = 0; i < 8; i++) h[i] = __float2half_rn(fixq_f(f[i]));
        *reinterpret_cast<uint4*>(g_XQ + base) = *reinterpret_cast<uint4*>(h);
    } else {
        int base = ((b - 256) * 256 + t) * 8;
        float4 v0 = *reinterpret_cast<const float4*>(w + base);
        float4 v1 = *reinterpret_cast<const float4*>(w + base + 4);
        float f[8] = {v0.x, v0.y, v0.z, v0.w, v1.x, v1.y, v1.z, v1.w};
        __half h[8];
        #pragma unroll
        for (int i = 0; i < 8; i++) h[i] = __float2half_rn(fixq_f(f[i]));
        *reinterpret_cast<uint4*>(g_WQ + base) = *reinterpret_cast<uint4*>(h);
    }
}

// ---------------------------------------------------------------------------
// GEMM: out[b,o] = qout(sum_k XQ[b,k] * WQ[o,k]) + bias[o]
// CTA tile 64x64, 512 threads / 16 warps.
// Warp-level split-K: k-group 0 (warps 0-7) does ks 0-1 of each BK=64 stage,
// k-group 1 (warps 8-15) does ks 2-3. Warp tile 16x32, warp grid 4x2 per group.
// Final smem reduction adds the two accumulator halves.
// Grid: (16, 8) = 128 CTAs.
// ---------------------------------------------------------------------------
#define BK        64
#define NIT       (IN_F / BK)       // 16
#define PITCH     72                // halves per smem row (144B; conflict-free)
#define MAT_B     (64 * PITCH * 2)  // bytes per matrix tile (9216)
#define STAGE_B   (2 * MAT_B)       // XQ, B tiles (18432)
#define NSTAGES   4
#define SMEM_BYTES (NSTAGES * STAGE_B)   // 73728

__global__ __launch_bounds__(512) void mvm_gemm_kernel(const float* __restrict__ bias,
                                                       float* __restrict__ out) {
    extern __shared__ __align__(128) __half smem[];

    const int tid  = threadIdx.x;
    const int lane = tid & 31;
    const int warp = tid >> 5;        // 0..15
    const int kg   = warp >> 3;       // k-group: 0 or 1
    const int wsub = warp & 7;        // warp id within group
    const int wm = wsub >> 1, wn = wsub & 1;   // 4x2 warp grid, warp tile 16x32
    const int bm0 = blockIdx.y * 64;
    const int bn0 = blockIdx.x * 64;

    float acc[4][4];
    #pragma unroll
    for (int nj = 0; nj < 4; ++nj)
        #pragma unroll
        for (int c = 0; c < 4; ++c) acc[nj][c] = 0.0f;

    const __half* gA = g_XQ + (size_t)bm0 * IN_F;
    const __half* gB = g_WQ + (size_t)bn0 * IN_F;

    // cp.async: 64 rows x 8 chunks(16B) per matrix = 512 chunks; 512 threads -> 1/matrix
    const int r0 = tid >> 3;          // 0..63
    const int ch = tid & 7;           // chunk 0..7
    const uint32_t smem_base = (uint32_t)__cvta_generic_to_shared(smem);

    auto prefetch = [&](int p) {
        const int s = p & (NSTAGES - 1);
        const uint32_t so = smem_base + s * STAGE_B;
        const int k0 = p * BK + ch * 8;
        const uint32_t d = so + (r0 * PITCH + ch * 8) * 2;
        cpa16(d,         gA + (size_t)r0 * IN_F + k0);
        cpa16(d + MAT_B, gB + (size_t)r0 * IN_F + k0);
        asm volatile("cp.async.commit_group;\n" ::: "memory");
    };

    prefetch(0); prefetch(1); prefetch(2);

    // Per-lane fragment byte offsets (within a stage); k-group offset = kg*2 ks = kg*64B
    const uint32_t kgo    = kg * 64;
    const uint32_t laneA  = ((wm * 16 + (lane & 15)) * PITCH + (lane >> 4) * 8) * 2 + kgo;
    const uint32_t laneB0 = ((wn * 32 + ((lane >> 4) & 1) * 8 + (lane & 7)) * PITCH
                             + ((lane >> 3) & 1) * 8) * 2 + kgo;
    const uint32_t laneB1 = laneB0 + 16 * PITCH * 2;

    for (int it = 0; it < NIT; ++it) {
        if      (it < NIT - 2)  asm volatile("cp.async.wait_group 2;\n" ::: "memory");
        else if (it == NIT - 2) asm volatile("cp.async.wait_group 1;\n" ::: "memory");
        else                    asm volatile("cp.async.wait_group 0;\n" ::: "memory");
        __syncthreads();
        if (it + 3 < NIT) prefetch(it + 3);

        const int s = it & (NSTAGES - 1);
        const uint32_t so   = smem_base + s * STAGE_B;
        const uint32_t aad  = so + laneA;
        const uint32_t bad0 = so + MAT_B + laneB0;
        const uint32_t bad1 = so + MAT_B + laneB1;

        // This k-group handles ks = kg*2 + {0,1}
        uint32_t aa[2][4], bb[2][2][4];
        ldmx4(aa[0], aad);
        ldmx4(bb[0][0], bad0);
        ldmx4(bb[0][1], bad1);
        ldmx4(aa[1], aad + 32);
        ldmx4(bb[1][0], bad0 + 32);
        ldmx4(bb[1][1], bad1 + 32);

        #pragma unroll
        for (int j = 0; j < 2; ++j)
            #pragma unroll
            for (int nj = 0; nj < 4; ++nj) {
                const uint32_t blo = bb[j][nj >> 1][(nj & 1) * 2];
                const uint32_t bhi = bb[j][nj >> 1][(nj & 1) * 2 + 1];
                mma16816(acc[nj], aa[j], blo, bhi);
            }
    }

    // ---- Cross-k-group reduction through smem ----
    float4* red = reinterpret_cast<float4*>(smem);
    __syncthreads();                  // all stages consumed; smem reusable
    if (kg == 1) {
        #pragma unroll
        for (int q = 0; q < 4; ++q) {
            float4 v;
            v.x = acc[q][0]; v.y = acc[q][1]; v.z = acc[q][2]; v.w = acc[q][3];
            red[(wsub * 4 + q) * 32 + lane] = v;
        }
    }
    __syncthreads();
    if (kg == 0) {
        const int gr = bm0 + wm * 16 + (lane >> 2);
        #pragma unroll
        for (int nj = 0; nj < 4; ++nj) {
            float4 o = red[(wsub * 4 + nj) * 32 + lane];
            const int gc = bn0 + wn * 32 + nj * 8 + (lane & 3) * 2;
            const float b0 = __ldg(&bias[gc]);
            const float b1 = __ldg(&bias[gc + 1]);
            float2 v0, v1;
            v0.x = qout(acc[nj][0] + o.x) + b0;
            v0.y = qout(acc[nj][1] + o.y) + b1;
            v1.x = qout(acc[nj][2] + o.z) + b0;
            v1.y = qout(acc[nj][3] + o.w) + b1;
            *reinterpret_cast<float2*>(&out[(size_t)gr * OUT_F + gc]) = v0;
            *reinterpret_cast<float2*>(&out[(size_t)(gr + 8) * OUT_F + gc]) = v1;
        }
    }
}

extern "C" void kernel_launch(void* const* d_in, const int* in_sizes, int n_in,
                              void* d_out, int out_size) {
    const float* x    = (const float*)d_in[0];   // [512,1024]
    const float* w    = (const float*)d_in[1];   // [1024,1024] (out_f, in_f)
    const float* bias = (const float*)d_in[2];   // [1024]
    float* out = (float*)d_out;                  // [512,1024] float32

    cudaFuncSetAttribute(mvm_gemm_kernel,
                         cudaFuncAttributeMaxDynamicSharedMemorySize, SMEM_BYTES);

    quant_kernel<<<768, 256>>>(x, w);
    dim3 grid(OUT_F / 64, B_DIM / 64);           // 16 x 8 = 128 CTAs
    mvm_gemm_kernel<<<grid, 512, SMEM_BYTES>>>(bias, out);
}